// round 16
// baseline (speedup 1.0000x reference)
#include <cuda_runtime.h>
#include <cstdint>

#define THREADS   256
#define DIN       100
#define HD        64
#define GG        10
#define NHEADS    5
#define CHUNK     25
#define MS1       128
#define MS2       256
#define XSTR      132
#define ASTR      128
#define B_MAX     262144

// ---------------- kernel1 shared layout (floats), phase-overlaid ----------------
#define OFF_W     0
#define OFF_A0    4400
#define OFF_XS0   6400
#define OFF_XS1   9700
#define OFF_DB0   13008
#define OFF_DB1   13072
#define OFF_DBB   13136
#define OFF_DBW   13152
#define SM1_FLOATS 13920
#define SM1_BYTES  (SM1_FLOATS * 4)        // 55,680 B -> 4 CTAs/SM

// ---------------- kernel2 shared layout (floats) ----------------
#define K2T       288
#define NSLOT     288
#define K2_W0     0          // 5*4100 = 20500
#define K2_TW0    20512
#define K2_B0     20848
#define K2_W1     21184
#define K2_TW1    21536
#define K2_B1     21544
#define K2_DS     21552                    // NSLOT
#define K2_PERM   (K2_DS + NSLOT)          // int[NSLOT]
#define K2_CNT    (K2_PERM + NSLOT)
#define K2_CUR    (K2_CNT + 8)
#define K2_OFFS   (K2_CUR + 8)
#define K2_HS     (K2_OFFS + 8)            // double buffer [2][8][256]
#define SM2_FLOATS (K2_HS + 2*8*256)
#define SM2_BYTES  (SM2_FLOATS * 4)        // ~104 KB -> 2 CTAs/SM

__device__ float g_hid[(size_t)HD * B_MAX];   // TRANSPOSED: [k][B], fp32

typedef unsigned long long ull;
struct u2 { ull x, y; };

#define FFMA2(d, a, b, c) \
    asm("fma.rn.f32x2 %0, %1, %2, %3;" : "=l"(d) : "l"(a), "l"(b), "l"(c))

__device__ __forceinline__ ull splat2(float a) {
    ull r; asm("mov.b64 %0, {%1, %1};" : "=l"(r) : "f"(a)); return r;
}
__device__ __forceinline__ ull pack2(float a, float b) {
    ull r; asm("mov.b64 %0, {%1, %2};" : "=l"(r) : "f"(a), "f"(b)); return r;
}
__device__ __forceinline__ void unpack2(ull v, float& a, float& b) {
    asm("mov.b64 {%0, %1}, %2;" : "=f"(a), "=f"(b) : "l"(v));
}
__device__ __forceinline__ unsigned int smaddr(const void* p) {
    unsigned int a;
    asm("{ .reg .u64 t; cvta.to.shared.u64 t, %1; cvt.u32.u64 %0, t; }"
        : "=r"(a) : "l"(p));
    return a;
}
#define CP_ASYNC4(sa, gp) \
    asm volatile("cp.async.ca.shared.global [%0], [%1], 4;" :: "r"(sa), "l"(gp))
#define CP_ASYNC16(sa, gp) \
    asm volatile("cp.async.ca.shared.global [%0], [%1], 16;" :: "r"(sa), "l"(gp))
#define CP_COMMIT()  asm volatile("cp.async.commit_group;")
#define CP_WAIT1()   asm volatile("cp.async.wait_group 1;")
#define CP_WAIT0()   asm volatile("cp.async.wait_group 0;")

// x as natural sample-pairs (no splat), WEIGHT splatted x4.
// acc[op*4+sp] = (samples m0+2sp, m0+2sp+1) for output n0+op.
// 3 LDS.128 + 4 MOV + 16 FFMA2 per k-step.
#define STEP_SPW(xbase, wbase, acc) do {                                       \
    u2 xs0 = ((const u2*)(xbase))[0];                                          \
    u2 xs1 = ((const u2*)(xbase))[1];                                          \
    float4 wf = *(const float4*)(wbase);                                       \
    ull w0s = splat2(wf.x), w1s = splat2(wf.y);                                \
    ull w2s = splat2(wf.z), w3s = splat2(wf.w);                                \
    FFMA2(acc[0],  xs0.x, w0s, acc[0]);  FFMA2(acc[1],  xs0.y, w0s, acc[1]);   \
    FFMA2(acc[2],  xs1.x, w0s, acc[2]);  FFMA2(acc[3],  xs1.y, w0s, acc[3]);   \
    FFMA2(acc[4],  xs0.x, w1s, acc[4]);  FFMA2(acc[5],  xs0.y, w1s, acc[5]);   \
    FFMA2(acc[6],  xs1.x, w1s, acc[6]);  FFMA2(acc[7],  xs1.y, w1s, acc[7]);   \
    FFMA2(acc[8],  xs0.x, w2s, acc[8]);  FFMA2(acc[9],  xs0.y, w2s, acc[9]);   \
    FFMA2(acc[10], xs1.x, w2s, acc[10]); FFMA2(acc[11], xs1.y, w2s, acc[11]);  \
    FFMA2(acc[12], xs0.x, w3s, acc[12]); FFMA2(acc[13], xs0.y, w3s, acc[13]);  \
    FFMA2(acc[14], xs1.x, w3s, acc[14]); FFMA2(acc[15], xs1.y, w3s, acc[15]);  \
} while (0)

// ======================= kernel 1: MLP GEMMs + density =======================
__global__ void __launch_bounds__(THREADS, 4)
drnet_mlp_kernel(const float* __restrict__ dosage, const float* __restrict__ x,
                 const float* __restrict__ dW0, const float* __restrict__ db0,
                 const float* __restrict__ dW1, const float* __restrict__ db1,
                 const float* __restrict__ dbW, const float* __restrict__ dbB,
                 float* __restrict__ out, int B)
{
    extern __shared__ float sm[];
    const int tid  = threadIdx.x;
    const int lane = tid & 31;
    const int wid  = tid >> 5;
    const int warpM = wid & 1, warpN = wid >> 1;
    const int tm = lane & 7,   tn = lane >> 3;
    const int m0 = warpM * 64 + tm * 8;
    const int n0 = warpN * 16 + tn * 4;
    const int mbase = blockIdx.x * MS1;

    // ---- kick off XS chunk0 via cp.async; stage dW0 + small params ----
    {
        const float* xsrc = x + (size_t)mbase * DIN;
        #pragma unroll
        for (int u = 0; u < 13; u++) {
            int i = tid + u * THREADS;
            if (i < MS1 * CHUNK) {
                unsigned int sa = smaddr(sm + OFF_XS0 + (i % CHUNK) * XSTR + i / CHUNK);
                CP_ASYNC4(sa, xsrc + (i / CHUNK) * DIN + (i % CHUNK));
            }
        }
        CP_COMMIT();
    }
    #pragma unroll 4
    for (int i = tid; i < DIN * HD; i += THREADS) sm[OFF_W + i] = dW0[i];
    for (int i = tid; i < HD * 11; i += THREADS) {
        int k = i / 11, j = i % 11;
        sm[OFF_DBW + k * 12 + j] = dbW[i];
    }
    if (tid < HD) { sm[OFF_DB0 + tid] = db0[tid]; sm[OFF_DB1 + tid] = db1[tid]; }
    if (tid < 11) sm[OFF_DBB + tid] = dbB[tid];

    // ---------------- layer0 GEMM, cp.async double-buffered ----------------
    ull acc[16];
    #pragma unroll
    for (int i = 0; i < 16; i++) acc[i] = 0ull;

    #pragma unroll 1
    for (int c = 0; c < DIN / CHUNK; c++) {
        const int xoff = (c & 1) ? OFF_XS1 : OFF_XS0;
        if (c < DIN / CHUNK - 1) {
            const int noff = (c & 1) ? OFF_XS0 : OFF_XS1;
            const float* xsrc = x + (size_t)mbase * DIN + (c + 1) * CHUNK;
            #pragma unroll
            for (int u = 0; u < 13; u++) {
                int i = tid + u * THREADS;
                if (i < MS1 * CHUNK) {
                    unsigned int sa = smaddr(sm + noff + (i % CHUNK) * XSTR + i / CHUNK);
                    CP_ASYNC4(sa, xsrc + (i / CHUNK) * DIN + (i % CHUNK));
                }
            }
            CP_COMMIT();
            CP_WAIT1();
        } else {
            CP_WAIT0();
        }
        __syncthreads();
        #pragma unroll 5
        for (int kk = 0; kk < CHUNK; kk++) {
            STEP_SPW(sm + xoff + kk * XSTR + m0,
                     sm + OFF_W + (c * CHUNK + kk) * HD + n0, acc);
        }
        __syncthreads();
    }
    // epilogue layer0: bias + relu -> A0 k-major [n][m]  (acc[op*4+sp] layout)
    {
        #pragma unroll
        for (int j = 0; j < 4; j++) {
            float bj = sm[OFF_DB0 + n0 + j];
            float v[8];
            #pragma unroll
            for (int sp = 0; sp < 4; sp++) {
                float e0, e1; unpack2(acc[j * 4 + sp], e0, e1);
                v[2*sp]   = fmaxf(e0 + bj, 0.0f);
                v[2*sp+1] = fmaxf(e1 + bj, 0.0f);
            }
            float* dst = sm + OFF_A0 + (n0 + j) * ASTR + m0;
            *(float4*)dst       = make_float4(v[0], v[1], v[2], v[3]);
            *(float4*)(dst + 4) = make_float4(v[4], v[5], v[6], v[7]);
        }
    }
    // restage dW1 into [0,4096)
    {
        const float4* src = (const float4*)dW1;
        #pragma unroll
        for (int i = tid; i < HD * HD / 4; i += THREADS)
            ((float4*)(sm + OFF_W))[i] = src[i];
    }
    __syncthreads();

    // ---------------- layer1 GEMM ----------------
    #pragma unroll
    for (int i = 0; i < 16; i++) acc[i] = 0ull;
    #pragma unroll 4
    for (int k = 0; k < HD; k++) {
        STEP_SPW(sm + OFF_A0 + k * ASTR + m0,
                 sm + OFF_W + k * HD + n0, acc);
    }
    __syncthreads();
    {
        #pragma unroll
        for (int j = 0; j < 4; j++) {
            float bj = sm[OFF_DB1 + n0 + j];
            float v[8];
            #pragma unroll
            for (int sp = 0; sp < 4; sp++) {
                float e0, e1; unpack2(acc[j * 4 + sp], e0, e1);
                v[2*sp]   = fmaxf(e0 + bj, 0.0f);
                v[2*sp+1] = fmaxf(e1 + bj, 0.0f);
            }
            float* dst = sm + OFF_A0 + (n0 + j) * ASTR + m0;
            *(float4*)dst       = make_float4(v[0], v[1], v[2], v[3]);
            *(float4*)(dst + 4) = make_float4(v[4], v[5], v[6], v[7]);
            float* gdst = g_hid + (size_t)(n0 + j) * B + mbase + m0;
            *(float4*)gdst       = make_float4(v[0], v[1], v[2], v[3]);
            *(float4*)(gdst + 4) = make_float4(v[4], v[5], v[6], v[7]);
        }
    }
    __syncthreads();

    // ---------------- density (thread-per-sample, tid < 128) ----------------
    if (tid < MS1) {
        const float t = dosage[mbase + tid];
        float logit[GG + 1];
        #pragma unroll
        for (int j = 0; j <= GG; j++) logit[j] = sm[OFF_DBB + j];
        #pragma unroll 4
        for (int k = 0; k < HD; k++) {
            float a = sm[OFF_A0 + k * ASTR + tid];
            const float4* d4 = (const float4*)(sm + OFF_DBW + k * 12);
            float4 da = d4[0], db_ = d4[1], dc = d4[2];
            logit[0] += a * da.x;  logit[1] += a * da.y;  logit[2]  += a * da.z;  logit[3] += a * da.w;
            logit[4] += a * db_.x; logit[5] += a * db_.y; logit[6]  += a * db_.z; logit[7] += a * db_.w;
            logit[8] += a * dc.x;  logit[9] += a * dc.y;  logit[10] += a * dc.z;
        }
        float m = logit[0];
        #pragma unroll
        for (int j = 1; j <= GG; j++) m = fmaxf(m, logit[j]);
        float p[GG + 1]; float psum = 0.0f;
        #pragma unroll
        for (int j = 0; j <= GG; j++) { p[j] = expf(logit[j] - m); psum += p[j]; }
        float pinv = 1.0f / psum;

        float tB = t * (float)GG;
        float U = ceilf(tB);
        float inter = 1.0f - (U - tB);
        int Ui = (int)U;
        int Li = Ui - 1; if (Li < 0) Li = 0;
        float pL = 0.0f, pU = 0.0f;
        #pragma unroll
        for (int j = 0; j <= GG; j++) {
            pL = (j == Li) ? p[j] : pL;
            pU = (j == Ui) ? p[j] : pU;
        }
        pL *= pinv; pU *= pinv;
        out[mbase + tid] = pL + (pU - pL) * inter;
    }
}

// ===== kernel 2: bucket-sorted warp-GEMM head, cp.async pipelined =====
__global__ void __launch_bounds__(K2T, 2)
drnet_head_kernel(const float* __restrict__ dosage,
                  const float* __restrict__ W0,  const float* __restrict__ tw0,
                  const float* __restrict__ b0,  const float* __restrict__ W1,
                  const float* __restrict__ tw1, const float* __restrict__ b1,
                  float* __restrict__ out, int B)
{
    extern __shared__ float sm[];
    int* iperm = (int*)(sm + K2_PERM);
    int* icnt  = (int*)(sm + K2_CNT);
    int* icur  = (int*)(sm + K2_CUR);
    int* ioffs = (int*)(sm + K2_OFFS);
    const int tid  = threadIdx.x;
    const int lane = tid & 31;
    const int wid  = tid >> 5;
    const int mbase = blockIdx.x * MS2;

    // issue hid chunk 0 (8 rows x 256 samples, unpermuted, coalesced) FIRST
    {
        #pragma unroll
        for (int u = 0; u < 2; u++) {
            int i = tid + u * K2T;
            if (i < 512) {
                int r = i >> 6, c4 = (i & 63) << 2;
                unsigned int sa = smaddr(sm + K2_HS + r * 256 + c4);
                CP_ASYNC16(sa, g_hid + (size_t)r * B + mbase + c4);
            }
        }
        CP_COMMIT();
    }

    // stage W0 (head stride 4100) + small params
    #pragma unroll 4
    for (int i = tid; i < NHEADS * HD * HD; i += K2T) {
        int h = i >> 12, r = i & 4095;
        sm[K2_W0 + h * 4100 + r] = W0[i];
    }
    for (int i = tid; i < NHEADS * HD; i += K2T) {
        int h = i / HD, j = i % HD;
        sm[K2_TW0 + h * 65 + j] = tw0[i];
        sm[K2_B0  + h * 65 + j] = b0[i];
        sm[K2_W1  + h * 68 + j] = W1[i];
    }
    if (tid < NHEADS) {
        sm[K2_TW1 + tid] = tw1[tid];
        sm[K2_B1  + tid] = b1[tid];
        icnt[tid] = 0;
    }
    for (int i = tid; i < NSLOT; i += K2T) { iperm[i] = -1; sm[K2_DS + i] = 0.0f; }
    __syncthreads();

    // counting sort by bucket, segments padded to multiple of 4
    float tmine = 0.0f; int bkt = 0;
    if (tid < MS2) {
        tmine = dosage[mbase + tid];
        bkt = (int)floorf(tmine * (float)NHEADS);
        if (bkt < 0) bkt = 0;
        if (bkt > NHEADS - 1) bkt = NHEADS - 1;
        atomicAdd(&icnt[bkt], 1);
    }
    __syncthreads();
    if (tid == 0) {
        int o = 0;
        #pragma unroll
        for (int h = 0; h < NHEADS; h++) {
            ioffs[h] = o; icur[h] = o;
            o += (icnt[h] + 3) & ~3;
        }
        ioffs[NHEADS] = o;
    }
    __syncthreads();
    if (tid < MS2) {
        int slot = atomicAdd(&icur[bkt], 1);
        iperm[slot] = tid;
        sm[K2_DS + slot] = tmine;
    }
    __syncthreads();

    // lane tile: 4 samples (slots sg..sg+3) x 16 outputs (n0..n0+15)
    const int sg = wid * 32 + (lane & 7) * 4;
    const int n0 = (lane >> 3) * 16;
    const int h  = (sg >= ioffs[1]) + (sg >= ioffs[2]) +
                   (sg >= ioffs[3]) + (sg >= ioffs[4]);

    // hoisted per-lane sample indices (pad slots -> 0, harmless)
    int sidx[4];
    float tg[4];
    #pragma unroll
    for (int si = 0; si < 4; si++) {
        int pm = iperm[sg + si];
        sidx[si] = pm < 0 ? 0 : pm;
        tg[si] = sm[K2_DS + sg + si];
    }

    ull acc[32];
    {
        const float* twp = sm + K2_TW0 + h * 65 + n0;
        const float* bbp = sm + K2_B0  + h * 65 + n0;
        #pragma unroll
        for (int si = 0; si < 4; si++)
            #pragma unroll
            for (int jj = 0; jj < 8; jj++)
                acc[si * 8 + jj] = pack2(fmaf(tg[si], twp[2*jj],   bbp[2*jj]),
                                         fmaf(tg[si], twp[2*jj+1], bbp[2*jj+1]));
    }

    const float* wh = sm + K2_W0 + h * 4100;
    #pragma unroll 1
    for (int cc = 0; cc < 8; cc++) {
        __syncthreads();   // prior compute on the buffer we are about to fill is done
        if (cc < 7) {
            const int nbuf = (cc + 1) & 1;
            #pragma unroll
            for (int u = 0; u < 2; u++) {
                int i = tid + u * K2T;
                if (i < 512) {
                    int r = i >> 6, c4 = (i & 63) << 2;
                    unsigned int sa = smaddr(sm + K2_HS + nbuf * 2048 + r * 256 + c4);
                    CP_ASYNC16(sa, g_hid + (size_t)((cc + 1) * 8 + r) * B + mbase + c4);
                }
            }
            CP_COMMIT();
            CP_WAIT1();
        } else {
            CP_WAIT0();
        }
        __syncthreads();   // chunk cc visible to all
        const float* hbuf = sm + K2_HS + (cc & 1) * 2048;
        #pragma unroll
        for (int kk = 0; kk < 8; kk++) {
            const float* hrow = hbuf + kk * 256;
            ull xs0 = splat2(hrow[sidx[0]]);
            ull xs1 = splat2(hrow[sidx[1]]);
            ull xs2 = splat2(hrow[sidx[2]]);
            ull xs3 = splat2(hrow[sidx[3]]);
            const u2* wp = (const u2*)(wh + (cc * 8 + kk) * HD + n0);
            u2 w0 = wp[0], w1 = wp[1], w2 = wp[2], w3 = wp[3];
            FFMA2(acc[0],  xs0, w0.x, acc[0]);  FFMA2(acc[1],  xs0, w0.y, acc[1]);
            FFMA2(acc[2],  xs0, w1.x, acc[2]);  FFMA2(acc[3],  xs0, w1.y, acc[3]);
            FFMA2(acc[4],  xs0, w2.x, acc[4]);  FFMA2(acc[5],  xs0, w2.y, acc[5]);
            FFMA2(acc[6],  xs0, w3.x, acc[6]);  FFMA2(acc[7],  xs0, w3.y, acc[7]);
            FFMA2(acc[8],  xs1, w0.x, acc[8]);  FFMA2(acc[9],  xs1, w0.y, acc[9]);
            FFMA2(acc[10], xs1, w1.x, acc[10]); FFMA2(acc[11], xs1, w1.y, acc[11]);
            FFMA2(acc[12], xs1, w2.x, acc[12]); FFMA2(acc[13], xs1, w2.y, acc[13]);
            FFMA2(acc[14], xs1, w3.x, acc[14]); FFMA2(acc[15], xs1, w3.y, acc[15]);
            FFMA2(acc[16], xs2, w0.x, acc[16]); FFMA2(acc[17], xs2, w0.y, acc[17]);
            FFMA2(acc[18], xs2, w1.x, acc[18]); FFMA2(acc[19], xs2, w1.y, acc[19]);
            FFMA2(acc[20], xs2, w2.x, acc[20]); FFMA2(acc[21], xs2, w2.y, acc[21]);
            FFMA2(acc[22], xs2, w3.x, acc[22]); FFMA2(acc[23], xs2, w3.y, acc[23]);
            FFMA2(acc[24], xs3, w0.x, acc[24]); FFMA2(acc[25], xs3, w0.y, acc[25]);
            FFMA2(acc[26], xs3, w1.x, acc[26]); FFMA2(acc[27], xs3, w1.y, acc[27]);
            FFMA2(acc[28], xs3, w2.x, acc[28]); FFMA2(acc[29], xs3, w2.y, acc[29]);
            FFMA2(acc[30], xs3, w3.x, acc[30]); FFMA2(acc[31], xs3, w3.y, acc[31]);
        }
    }

    // epilogue: relu + dot with W1 slice, reduce across 4 n-groups
    float qp[4];
    {
        const float* w1p = sm + K2_W1 + h * 68 + n0;
        #pragma unroll
        for (int si = 0; si < 4; si++) {
            float q = 0.0f;
            #pragma unroll
            for (int jj = 0; jj < 8; jj++) {
                float lo, hi; unpack2(acc[si * 8 + jj], lo, hi);
                q += fmaxf(lo, 0.0f) * w1p[2*jj+0];
                q += fmaxf(hi, 0.0f) * w1p[2*jj+1];
            }
            qp[si] = q;
        }
    }
    #pragma unroll
    for (int si = 0; si < 4; si++) {
        qp[si] += __shfl_xor_sync(0xFFFFFFFF, qp[si], 8);
        qp[si] += __shfl_xor_sync(0xFFFFFFFF, qp[si], 16);
    }
    if (lane < 8) {
        #pragma unroll
        for (int si = 0; si < 4; si++) {
            int slot = sg + si;
            int pm = iperm[slot];
            if (pm >= 0) {
                float t = sm[K2_DS + slot];
                out[B + mbase + pm] =
                    qp[si] + fmaf(t, sm[K2_TW1 + h], sm[K2_B1 + h]);
            }
        }
    }
}

extern "C" void kernel_launch(void* const* d_in, const int* in_sizes, int n_in,
                              void* d_out, int out_size)
{
    const float* dosage = (const float*)d_in[0];
    const float* x      = (const float*)d_in[1];
    const float* dW0    = (const float*)d_in[2];
    const float* db0    = (const float*)d_in[3];
    const float* dW1    = (const float*)d_in[4];
    const float* db1    = (const float*)d_in[5];
    const float* dbW    = (const float*)d_in[6];
    const float* dbB    = (const float*)d_in[7];
    const float* W0     = (const float*)d_in[8];
    const float* tw0    = (const float*)d_in[9];
    const float* b0     = (const float*)d_in[10];
    const float* W1     = (const float*)d_in[11];
    const float* tw1    = (const float*)d_in[12];
    const float* b1     = (const float*)d_in[13];
    float* out = (float*)d_out;

    int B = in_sizes[0];

    cudaFuncSetAttribute(drnet_mlp_kernel,
                         cudaFuncAttributeMaxDynamicSharedMemorySize, SM1_BYTES);
    cudaFuncSetAttribute(drnet_head_kernel,
                         cudaFuncAttributeMaxDynamicSharedMemorySize, SM2_BYTES);

    drnet_mlp_kernel<<<B / MS1, THREADS, SM1_BYTES>>>(
        dosage, x, dW0, db0, dW1, db1, dbW, dbB, out, B);
    drnet_head_kernel<<<B / MS2, K2T, SM2_BYTES>>>(
        dosage, W0, tw0, b0, W1, tw1, b1, out, B);
}

// round 17
// speedup vs baseline: 1.8028x; 1.8028x over previous
#include <cuda_runtime.h>
#include <cstdint>

#define THREADS   256
#define DIN       100
#define HD        64
#define GG        10
#define NHEADS    5
#define CHUNK     25
#define MS1       256
#define MS2       256
#define XSTR2     260
#define B_MAX     262144

// ---------------- kernel1 shared layout (floats), phase-overlaid ----------------
// Phase A (layer0):  [0: dW0 6400][XS0 6500][XS1 6500]
// Phase B (layer1+): [0: dW1 4096][4400: A0 64*260=16640]
#define OFF_W     0
#define OFF_A0    4400      // ends 21040
#define OFF_XS0   6400      // ends 12900
#define OFF_XS1   12900     // ends 19400
#define OFF_DB0   21040
#define OFF_DB1   21104
#define OFF_DBB   21168     // 12 (+4 pad)
#define OFF_DBW   21184     // 768
#define SM1_FLOATS 21952
#define SM1_BYTES  (SM1_FLOATS * 4)        // 87,808 B -> 2 CTAs/SM

// ---------------- kernel2 shared layout (floats) — R15/R10 exact ----------------
#define K2T       288
#define NSLOT     288
#define K2_W0     0          // 5*4100 = 20500
#define K2_TW0    20512
#define K2_B0     20848
#define K2_W1     21184
#define K2_TW1    21536
#define K2_B1     21544
#define K2_DS     21552
#define K2_PERM   (K2_DS + NSLOT)
#define K2_INV    (K2_PERM + NSLOT)
#define K2_CNT    (K2_INV + 256)
#define K2_CUR    (K2_CNT + 8)
#define K2_OFFS   (K2_CUR + 8)
#define K2_HS     (K2_OFFS + 8)
#define SM2_FLOATS (K2_HS + 16*NSLOT)
#define SM2_BYTES  (SM2_FLOATS * 4)        // 108,064 B -> 2 CTAs/SM

__device__ float g_hid[(size_t)HD * B_MAX];   // TRANSPOSED: [k][B], fp32

typedef unsigned long long ull;
struct u2 { ull x, y; };

#define FFMA2(d, a, b, c) \
    asm("fma.rn.f32x2 %0, %1, %2, %3;" : "=l"(d) : "l"(a), "l"(b), "l"(c))

__device__ __forceinline__ ull splat2(float a) {
    ull r; asm("mov.b64 %0, {%1, %1};" : "=l"(r) : "f"(a)); return r;
}
__device__ __forceinline__ ull pack2(float a, float b) {
    ull r; asm("mov.b64 %0, {%1, %2};" : "=l"(r) : "f"(a), "f"(b)); return r;
}
__device__ __forceinline__ void unpack2(ull v, float& a, float& b) {
    asm("mov.b64 {%0, %1}, %2;" : "=f"(a), "=f"(b) : "l"(v));
}
__device__ __forceinline__ unsigned int smaddr(const void* p) {
    unsigned int a;
    asm("{ .reg .u64 t; cvta.to.shared.u64 t, %1; cvt.u32.u64 %0, t; }"
        : "=r"(a) : "l"(p));
    return a;
}
#define CP_ASYNC4(sa, gp) \
    asm volatile("cp.async.ca.shared.global [%0], [%1], 4;" :: "r"(sa), "l"(gp))
#define CP_COMMIT()  asm volatile("cp.async.commit_group;")
#define CP_WAIT1()   asm volatile("cp.async.wait_group 1;")
#define CP_WAIT0()   asm volatile("cp.async.wait_group 0;")

// 8 samples x 8 outputs, proven STEP84 dataflow: x splatted ONCE, two weight
// u2-pairs (n0..n0+3, n0+4..n0+7), two acc banks. 2 x-LDS + 2 w-LDS + 8 MOV + 32 FFMA2.
#define STEP88(xa, xb, wv0, wv1, a0, a1) do {                                    \
    ull xv;                                                                      \
    xv = splat2((xa).x); FFMA2(a0[0], xv,(wv0).x,a0[0]);  FFMA2(a0[1], xv,(wv0).y,a0[1]);   \
                         FFMA2(a1[0], xv,(wv1).x,a1[0]);  FFMA2(a1[1], xv,(wv1).y,a1[1]);   \
    xv = splat2((xa).y); FFMA2(a0[2], xv,(wv0).x,a0[2]);  FFMA2(a0[3], xv,(wv0).y,a0[3]);   \
                         FFMA2(a1[2], xv,(wv1).x,a1[2]);  FFMA2(a1[3], xv,(wv1).y,a1[3]);   \
    xv = splat2((xa).z); FFMA2(a0[4], xv,(wv0).x,a0[4]);  FFMA2(a0[5], xv,(wv0).y,a0[5]);   \
                         FFMA2(a1[4], xv,(wv1).x,a1[4]);  FFMA2(a1[5], xv,(wv1).y,a1[5]);   \
    xv = splat2((xa).w); FFMA2(a0[6], xv,(wv0).x,a0[6]);  FFMA2(a0[7], xv,(wv0).y,a0[7]);   \
                         FFMA2(a1[6], xv,(wv1).x,a1[6]);  FFMA2(a1[7], xv,(wv1).y,a1[7]);   \
    xv = splat2((xb).x); FFMA2(a0[8], xv,(wv0).x,a0[8]);  FFMA2(a0[9], xv,(wv0).y,a0[9]);   \
                         FFMA2(a1[8], xv,(wv1).x,a1[8]);  FFMA2(a1[9], xv,(wv1).y,a1[9]);   \
    xv = splat2((xb).y); FFMA2(a0[10],xv,(wv0).x,a0[10]); FFMA2(a0[11],xv,(wv0).y,a0[11]);  \
                         FFMA2(a1[10],xv,(wv1).x,a1[10]); FFMA2(a1[11],xv,(wv1).y,a1[11]);  \
    xv = splat2((xb).z); FFMA2(a0[12],xv,(wv0).x,a0[12]); FFMA2(a0[13],xv,(wv0).y,a0[13]);  \
                         FFMA2(a1[12],xv,(wv1).x,a1[12]); FFMA2(a1[13],xv,(wv1).y,a1[13]);  \
    xv = splat2((xb).w); FFMA2(a0[14],xv,(wv0).x,a0[14]); FFMA2(a0[15],xv,(wv0).y,a0[15]);  \
                         FFMA2(a1[14],xv,(wv1).x,a1[14]); FFMA2(a1[15],xv,(wv1).y,a1[15]);  \
} while (0)

// ======================= kernel 1: MLP GEMMs + density =======================
__global__ void __launch_bounds__(THREADS, 2)
drnet_mlp_kernel(const float* __restrict__ dosage, const float* __restrict__ x,
                 const float* __restrict__ dW0, const float* __restrict__ db0,
                 const float* __restrict__ dW1, const float* __restrict__ db1,
                 const float* __restrict__ dbW, const float* __restrict__ dbB,
                 float* __restrict__ out, int B)
{
    extern __shared__ float sm[];
    const int tid  = threadIdx.x;
    const int lane = tid & 31;
    const int wid  = tid >> 5;
    const int warpM = wid & 3, warpN = wid >> 2;   // 4 M-warps x 2 N-warps
    const int tm = lane & 7,   tn = lane >> 3;
    const int m0 = warpM * 64 + tm * 8;            // 8 samples of 256
    const int n0 = warpN * 32 + tn * 8;            // 8 outputs of 64
    const int mbase = blockIdx.x * MS1;

    // ---- kick off XS chunk0 via cp.async; stage dW0 + small params ----
    {
        const float* xsrc = x + (size_t)mbase * DIN;
        #pragma unroll
        for (int u = 0; u < 25; u++) {
            int i = tid + u * THREADS;   // 25*256 = 6400 exactly
            unsigned int sa = smaddr(sm + OFF_XS0 + (i % CHUNK) * XSTR2 + i / CHUNK);
            CP_ASYNC4(sa, xsrc + (i / CHUNK) * DIN + (i % CHUNK));
        }
        CP_COMMIT();
    }
    #pragma unroll 4
    for (int i = tid; i < DIN * HD; i += THREADS) sm[OFF_W + i] = dW0[i];
    for (int i = tid; i < HD * 11; i += THREADS) {
        int k = i / 11, j = i % 11;
        sm[OFF_DBW + k * 12 + j] = dbW[i];
    }
    if (tid < HD) { sm[OFF_DB0 + tid] = db0[tid]; sm[OFF_DB1 + tid] = db1[tid]; }
    if (tid < 11) sm[OFF_DBB + tid] = dbB[tid];

    // ---------------- layer0 GEMM, cp.async double-buffered ----------------
    ull a0b[16], a1b[16];
    #pragma unroll
    for (int i = 0; i < 16; i++) { a0b[i] = 0ull; a1b[i] = 0ull; }

    #pragma unroll 1
    for (int c = 0; c < DIN / CHUNK; c++) {
        const int xoff = (c & 1) ? OFF_XS1 : OFF_XS0;
        if (c < DIN / CHUNK - 1) {
            const int noff = (c & 1) ? OFF_XS0 : OFF_XS1;
            const float* xsrc = x + (size_t)mbase * DIN + (c + 1) * CHUNK;
            #pragma unroll
            for (int u = 0; u < 25; u++) {
                int i = tid + u * THREADS;
                unsigned int sa = smaddr(sm + noff + (i % CHUNK) * XSTR2 + i / CHUNK);
                CP_ASYNC4(sa, xsrc + (i / CHUNK) * DIN + (i % CHUNK));
            }
            CP_COMMIT();
            CP_WAIT1();
        } else {
            CP_WAIT0();
        }
        __syncthreads();
        #pragma unroll 5
        for (int kk = 0; kk < CHUNK; kk++) {
            const float4* xp = (const float4*)(sm + xoff + kk * XSTR2 + m0);
            float4 xa = xp[0], xb = xp[1];
            const u2* wp = (const u2*)(sm + OFF_W + (c * CHUNK + kk) * HD + n0);
            u2 wv0 = wp[0], wv1 = wp[1];
            STEP88(xa, xb, wv0, wv1, a0b, a1b);
        }
        __syncthreads();
    }
    // epilogue layer0: bias + relu -> A0 k-major [n][m] (stride 260)
    {
        #pragma unroll
        for (int half = 0; half < 2; half++) {
            const ull* ap = half ? a1b : a0b;
            #pragma unroll
            for (int j = 0; j < 4; j++) {
                int p = j >> 1, hbit = j & 1;
                int n = n0 + half * 4 + j;
                float bj = sm[OFF_DB0 + n];
                float v[8];
                #pragma unroll
                for (int s = 0; s < 8; s++) {
                    float e0, e1; unpack2(ap[s * 2 + p], e0, e1);
                    v[s] = fmaxf((hbit ? e1 : e0) + bj, 0.0f);
                }
                float* dst = sm + OFF_A0 + n * XSTR2 + m0;
                *(float4*)dst       = make_float4(v[0], v[1], v[2], v[3]);
                *(float4*)(dst + 4) = make_float4(v[4], v[5], v[6], v[7]);
            }
        }
    }
    // restage dW1 into [0,4096) (below A0 at 4400)
    {
        const float4* src = (const float4*)dW1;
        #pragma unroll
        for (int i = tid; i < HD * HD / 4; i += THREADS)
            ((float4*)(sm + OFF_W))[i] = src[i];
    }
    __syncthreads();

    // ---------------- layer1 GEMM ----------------
    #pragma unroll
    for (int i = 0; i < 16; i++) { a0b[i] = 0ull; a1b[i] = 0ull; }
    #pragma unroll 4
    for (int k = 0; k < HD; k++) {
        const float4* xp = (const float4*)(sm + OFF_A0 + k * XSTR2 + m0);
        float4 xa = xp[0], xb = xp[1];
        const u2* wp = (const u2*)(sm + OFF_W + k * HD + n0);
        u2 wv0 = wp[0], wv1 = wp[1];
        STEP88(xa, xb, wv0, wv1, a0b, a1b);
    }
    __syncthreads();   // all A0 reads complete before overwrite
    {
        #pragma unroll
        for (int half = 0; half < 2; half++) {
            const ull* ap = half ? a1b : a0b;
            #pragma unroll
            for (int j = 0; j < 4; j++) {
                int p = j >> 1, hbit = j & 1;
                int n = n0 + half * 4 + j;
                float bj = sm[OFF_DB1 + n];
                float v[8];
                #pragma unroll
                for (int s = 0; s < 8; s++) {
                    float e0, e1; unpack2(ap[s * 2 + p], e0, e1);
                    v[s] = fmaxf((hbit ? e1 : e0) + bj, 0.0f);
                }
                float* dst = sm + OFF_A0 + n * XSTR2 + m0;
                *(float4*)dst       = make_float4(v[0], v[1], v[2], v[3]);
                *(float4*)(dst + 4) = make_float4(v[4], v[5], v[6], v[7]);
                float* gdst = g_hid + (size_t)n * B + mbase + m0;
                *(float4*)gdst       = make_float4(v[0], v[1], v[2], v[3]);
                *(float4*)(gdst + 4) = make_float4(v[4], v[5], v[6], v[7]);
            }
        }
    }
    __syncthreads();

    // ---------------- density (thread-per-sample, all 256) ----------------
    {
        const float t = dosage[mbase + tid];
        float logit[GG + 1];
        #pragma unroll
        for (int j = 0; j <= GG; j++) logit[j] = sm[OFF_DBB + j];
        #pragma unroll 4
        for (int k = 0; k < HD; k++) {
            float a = sm[OFF_A0 + k * XSTR2 + tid];
            const float4* d4 = (const float4*)(sm + OFF_DBW + k * 12);
            float4 da = d4[0], db_ = d4[1], dc = d4[2];
            logit[0] += a * da.x;  logit[1] += a * da.y;  logit[2]  += a * da.z;  logit[3] += a * da.w;
            logit[4] += a * db_.x; logit[5] += a * db_.y; logit[6]  += a * db_.z; logit[7] += a * db_.w;
            logit[8] += a * dc.x;  logit[9] += a * dc.y;  logit[10] += a * dc.z;
        }
        float m = logit[0];
        #pragma unroll
        for (int j = 1; j <= GG; j++) m = fmaxf(m, logit[j]);
        float p[GG + 1]; float psum = 0.0f;
        #pragma unroll
        for (int j = 0; j <= GG; j++) { p[j] = expf(logit[j] - m); psum += p[j]; }
        float pinv = 1.0f / psum;

        float tB = t * (float)GG;
        float U = ceilf(tB);
        float inter = 1.0f - (U - tB);
        int Ui = (int)U;
        int Li = Ui - 1; if (Li < 0) Li = 0;
        float pL = 0.0f, pU = 0.0f;
        #pragma unroll
        for (int j = 0; j <= GG; j++) {
            pL = (j == Li) ? p[j] : pL;
            pU = (j == Ui) ? p[j] : pU;
        }
        pL *= pinv; pU *= pinv;
        out[mbase + tid] = pL + (pU - pL) * inter;
    }
}

// ============ kernel 2: bucket-sorted warp-GEMM head (R15 exact) ============
__global__ void __launch_bounds__(K2T, 2)
drnet_head_kernel(const float* __restrict__ dosage,
                  const float* __restrict__ W0,  const float* __restrict__ tw0,
                  const float* __restrict__ b0,  const float* __restrict__ W1,
                  const float* __restrict__ tw1, const float* __restrict__ b1,
                  float* __restrict__ out, int B)
{
    extern __shared__ float sm[];
    int* iperm = (int*)(sm + K2_PERM);
    int* iinv  = (int*)(sm + K2_INV);
    int* icnt  = (int*)(sm + K2_CNT);
    int* icur  = (int*)(sm + K2_CUR);
    int* ioffs = (int*)(sm + K2_OFFS);
    const int tid  = threadIdx.x;
    const int lane = tid & 31;
    const int wid  = tid >> 5;
    const int mbase = blockIdx.x * MS2;

    #pragma unroll 4
    for (int i = tid; i < NHEADS * HD * HD; i += K2T) {
        int h = i >> 12, r = i & 4095;
        sm[K2_W0 + h * 4100 + r] = W0[i];
    }
    for (int i = tid; i < NHEADS * HD; i += K2T) {
        int h = i / HD, j = i % HD;
        sm[K2_TW0 + h * 65 + j] = tw0[i];
        sm[K2_B0  + h * 65 + j] = b0[i];
        sm[K2_W1  + h * 68 + j] = W1[i];
    }
    if (tid < NHEADS) {
        sm[K2_TW1 + tid] = tw1[tid];
        sm[K2_B1  + tid] = b1[tid];
        icnt[tid] = 0;
    }
    for (int i = tid; i < NSLOT; i += K2T) { iperm[i] = -1; sm[K2_DS + i] = 0.0f; }
    __syncthreads();

    float tmine = 0.0f; int bkt = 0;
    if (tid < MS2) {
        tmine = dosage[mbase + tid];
        bkt = (int)floorf(tmine * (float)NHEADS);
        if (bkt < 0) bkt = 0;
        if (bkt > NHEADS - 1) bkt = NHEADS - 1;
        atomicAdd(&icnt[bkt], 1);
    }
    __syncthreads();
    if (tid == 0) {
        int o = 0;
        #pragma unroll
        for (int h = 0; h < NHEADS; h++) {
            ioffs[h] = o; icur[h] = o;
            o += (icnt[h] + 3) & ~3;
        }
        ioffs[NHEADS] = o;
    }
    __syncthreads();
    if (tid < MS2) {
        int slot = atomicAdd(&icur[bkt], 1);
        iperm[slot] = tid;
        iinv[tid] = slot;
        sm[K2_DS + slot] = tmine;
    }
    __syncthreads();

    const int sg = wid * 32 + (lane & 7) * 4;
    const int n0 = (lane >> 3) * 16;
    const int h  = (sg >= ioffs[1]) + (sg >= ioffs[2]) +
                   (sg >= ioffs[3]) + (sg >= ioffs[4]);

    float tg[4];
    #pragma unroll
    for (int si = 0; si < 4; si++) tg[si] = sm[K2_DS + sg + si];

    ull acc[32];
    {
        const float* twp = sm + K2_TW0 + h * 65 + n0;
        const float* bbp = sm + K2_B0  + h * 65 + n0;
        #pragma unroll
        for (int si = 0; si < 4; si++)
            #pragma unroll
            for (int jj = 0; jj < 8; jj++)
                acc[si * 8 + jj] = pack2(fmaf(tg[si], twp[2*jj],   bbp[2*jj]),
                                         fmaf(tg[si], twp[2*jj+1], bbp[2*jj+1]));
    }

    const float* wh = sm + K2_W0 + h * 4100;
    #pragma unroll 1
    for (int kc = 0; kc < 4; kc++) {
        __syncthreads();
        #pragma unroll
        for (int i = tid; i < 16 * MS2; i += K2T) {
            int r = i >> 8, c = i & 255;
            sm[K2_HS + r * NSLOT + iinv[c]] =
                g_hid[(size_t)(kc * 16 + r) * B + mbase + c];
        }
        __syncthreads();
        #pragma unroll
        for (int kk = 0; kk < 16; kk++) {
            float4 xv = *(const float4*)(sm + K2_HS + kk * NSLOT + sg);
            const u2* wp = (const u2*)(wh + (kc * 16 + kk) * HD + n0);
            u2 w0 = wp[0], w1 = wp[1], w2 = wp[2], w3 = wp[3];
            #pragma unroll
            for (int si = 0; si < 4; si++) {
                ull xs = splat2(((const float*)&xv)[si]);
                FFMA2(acc[si*8+0], xs, w0.x, acc[si*8+0]);
                FFMA2(acc[si*8+1], xs, w0.y, acc[si*8+1]);
                FFMA2(acc[si*8+2], xs, w1.x, acc[si*8+2]);
                FFMA2(acc[si*8+3], xs, w1.y, acc[si*8+3]);
                FFMA2(acc[si*8+4], xs, w2.x, acc[si*8+4]);
                FFMA2(acc[si*8+5], xs, w2.y, acc[si*8+5]);
                FFMA2(acc[si*8+6], xs, w3.x, acc[si*8+6]);
                FFMA2(acc[si*8+7], xs, w3.y, acc[si*8+7]);
            }
        }
    }

    float qp[4];
    {
        const float* w1p = sm + K2_W1 + h * 68 + n0;
        #pragma unroll
        for (int si = 0; si < 4; si++) {
            float q = 0.0f;
            #pragma unroll
            for (int jj = 0; jj < 8; jj++) {
                float lo, hi; unpack2(acc[si * 8 + jj], lo, hi);
                q += fmaxf(lo, 0.0f) * w1p[2*jj+0];
                q += fmaxf(hi, 0.0f) * w1p[2*jj+1];
            }
            qp[si] = q;
        }
    }
    #pragma unroll
    for (int si = 0; si < 4; si++) {
        qp[si] += __shfl_xor_sync(0xFFFFFFFF, qp[si], 8);
        qp[si] += __shfl_xor_sync(0xFFFFFFFF, qp[si], 16);
    }
    if (lane < 8) {
        #pragma unroll
        for (int si = 0; si < 4; si++) {
            int slot = sg + si;
            int pm = iperm[slot];
            if (pm >= 0) {
                float t = sm[K2_DS + slot];
                out[B + mbase + pm] =
                    qp[si] + fmaf(t, sm[K2_TW1 + h], sm[K2_B1 + h]);
            }
        }
    }
}

extern "C" void kernel_launch(void* const* d_in, const int* in_sizes, int n_in,
                              void* d_out, int out_size)
{
    const float* dosage = (const float*)d_in[0];
    const float* x      = (const float*)d_in[1];
    const float* dW0    = (const float*)d_in[2];
    const float* db0    = (const float*)d_in[3];
    const float* dW1    = (const float*)d_in[4];
    const float* db1    = (const float*)d_in[5];
    const float* dbW    = (const float*)d_in[6];
    const float* dbB    = (const float*)d_in[7];
    const float* W0     = (const float*)d_in[8];
    const float* tw0    = (const float*)d_in[9];
    const float* b0     = (const float*)d_in[10];
    const float* W1     = (const float*)d_in[11];
    const float* tw1    = (const float*)d_in[12];
    const float* b1     = (const float*)d_in[13];
    float* out = (float*)d_out;

    int B = in_sizes[0];

    cudaFuncSetAttribute(drnet_mlp_kernel,
                         cudaFuncAttributeMaxDynamicSharedMemorySize, SM1_BYTES);
    cudaFuncSetAttribute(drnet_head_kernel,
                         cudaFuncAttributeMaxDynamicSharedMemorySize, SM2_BYTES);

    drnet_mlp_kernel<<<B / MS1, THREADS, SM1_BYTES>>>(
        dosage, x, dW0, db0, dW1, db1, dbW, dbB, out, B);
    drnet_head_kernel<<<B / MS2, K2T, SM2_BYTES>>>(
        dosage, W0, tw0, b0, W1, tw1, b1, out, B);
}